// round 1
// baseline (speedup 1.0000x reference)
#include <cuda_runtime.h>

#define T_SEQ 34
#define ROWS 8
#define NT (T_SEQ * ROWS)
#define VCB 14

__device__ __forceinline__ void ln6(const float* x, const float* g, const float* b, float* o) {
    float mu = (x[0] + x[1] + x[2] + x[3] + x[4] + x[5]) * (1.0f / 6.0f);
    float var = 0.0f;
#pragma unroll
    for (int d = 0; d < 6; d++) { float dd = x[d] - mu; var += dd * dd; }
    var *= (1.0f / 6.0f);
    float inv = rsqrtf(var + 1e-5f);
#pragma unroll
    for (int d = 0; d < 6; d++) o[d] = (x[d] - mu) * inv * g[d] + b[d];
}

__global__ __launch_bounds__(NT) void add_tf_kernel(
    const int* __restrict__ idx,
    const float* __restrict__ tok_emb, const float* __restrict__ pos_enc,
    const float* __restrict__ qw, const float* __restrict__ kw, const float* __restrict__ vw,
    const float* __restrict__ outw,
    const float* __restrict__ ln1g, const float* __restrict__ ln1b,
    const float* __restrict__ ln2g, const float* __restrict__ ln2b,
    const float* __restrict__ lnfg, const float* __restrict__ lnfb,
    const float* __restrict__ fw1, const float* __restrict__ fb1,
    const float* __restrict__ fw2, const float* __restrict__ fb2,
    const float* __restrict__ headw,
    float* __restrict__ out)
{
    __shared__ float s_te[42], s_pe[102];
    __shared__ float s_qw[18], s_kw[18], s_vw[18], s_ow[36];
    __shared__ float s_w1[18], s_b1[3], s_w2[18], s_b2[6];
    __shared__ float s_l1g[6], s_l1b[6], s_l2g[6], s_l2b[6], s_lfg[6], s_lfb[6];
    __shared__ float s_hw[18];
    __shared__ float s_wlog[84];
    __shared__ float4 sK[2][ROWS][35];   // [head][row][t], padded stride 35 -> conflict-free
    __shared__ float4 sV[2][ROWS][35];
    __shared__ float s_out[ROWS * T_SEQ * VCB];  // 3808 floats

    const int r = threadIdx.x;   // row within block (0..7)
    const int t = threadIdx.y;   // position (0..33)
    const int tid = t * ROWS + r;

    // ---- cooperative weight staging ----
    for (int i = tid; i < 42; i += NT) s_te[i] = tok_emb[i];
    for (int i = tid; i < 102; i += NT) s_pe[i] = pos_enc[i];
    for (int i = tid; i < 18; i += NT) {
        s_qw[i] = qw[i]; s_kw[i] = kw[i]; s_vw[i] = vw[i];
        s_w1[i] = fw1[i]; s_w2[i] = fw2[i]; s_hw[i] = headw[i];
    }
    for (int i = tid; i < 36; i += NT) s_ow[i] = outw[i];
    for (int i = tid; i < 6; i += NT) {
        s_l1g[i] = ln1g[i]; s_l1b[i] = ln1b[i];
        s_l2g[i] = ln2g[i]; s_l2b[i] = ln2b[i];
        s_lfg[i] = lnfg[i]; s_lfb[i] = lnfb[i];
        s_b2[i] = fb2[i];
    }
    for (int i = tid; i < 3; i += NT) s_b1[i] = fb1[i];
    __syncthreads();

    // fused logits matrix: Wlog[v][d] = sum_c tok_emb[v][c] * head_w[c][d]
    for (int i = tid; i < 84; i += NT) {
        int v = i / 6, d = i % 6;
        s_wlog[i] = s_te[v * 3 + 0] * s_hw[0 * 6 + d]
                  + s_te[v * 3 + 1] * s_hw[1 * 6 + d]
                  + s_te[v * 3 + 2] * s_hw[2 * 6 + d];
    }

    // ---- per-token pre-attention ----
    const int b = blockIdx.x * ROWS + r;
    const int tok = idx[(size_t)b * T_SEQ + t];

    float x0[6];
    x0[0] = s_te[tok * 3 + 0]; x0[1] = s_te[tok * 3 + 1]; x0[2] = s_te[tok * 3 + 2];
    x0[3] = s_pe[t * 3 + 0];   x0[4] = s_pe[t * 3 + 1];   x0[5] = s_pe[t * 3 + 2];

    float h1[6];
    ln6(x0, s_l1g, s_l1b, h1);

    float q[6], kk[6], vv[6];
#pragma unroll
    for (int o = 0; o < 6; o++) {
        q[o]  = h1[3] * s_qw[o * 3 + 0] + h1[4] * s_qw[o * 3 + 1] + h1[5] * s_qw[o * 3 + 2];
        kk[o] = h1[3] * s_kw[o * 3 + 0] + h1[4] * s_kw[o * 3 + 1] + h1[5] * s_kw[o * 3 + 2];
        vv[o] = h1[0] * s_vw[o * 3 + 0] + h1[1] * s_vw[o * 3 + 1] + h1[2] * s_vw[o * 3 + 2];
    }
    sK[0][r][t] = make_float4(kk[0], kk[1], kk[2], 0.0f);
    sK[1][r][t] = make_float4(kk[3], kk[4], kk[5], 0.0f);
    sV[0][r][t] = make_float4(vv[0], vv[1], vv[2], 0.0f);
    sV[1][r][t] = make_float4(vv[3], vv[4], vv[5], 0.0f);
    __syncthreads();

    // ---- causal attention (no max-subtraction: |score| <= ~26, fp32-safe) ----
    float o6[6];
    const float rs3 = 0.57735026918962576f;
#pragma unroll
    for (int hh = 0; hh < 2; hh++) {
        float q0 = q[hh * 3 + 0], q1 = q[hh * 3 + 1], q2 = q[hh * 3 + 2];
        float a0 = 0.0f, a1 = 0.0f, a2 = 0.0f, ssum = 0.0f;
        for (int j = 0; j <= t; j++) {
            float4 kj = sK[hh][r][j];
            float s = (q0 * kj.x + q1 * kj.y + q2 * kj.z) * rs3;
            float e = __expf(s);
            float4 vj = sV[hh][r][j];
            ssum += e;
            a0 += e * vj.x; a1 += e * vj.y; a2 += e * vj.z;
        }
        float inv = 1.0f / ssum;
        o6[hh * 3 + 0] = a0 * inv;
        o6[hh * 3 + 1] = a1 * inv;
        o6[hh * 3 + 2] = a2 * inv;
    }

    // ---- out-proj + residual ----
    float xa[6];
#pragma unroll
    for (int d = 0; d < 6; d++) {
        float a = x0[d];
#pragma unroll
        for (int o = 0; o < 6; o++) a += o6[o] * s_ow[d * 6 + o];
        xa[d] = a;
    }

    // ---- FFN (exact GELU) + residual ----
    float h2[6];
    ln6(xa, s_l2g, s_l2b, h2);
    float g3[3];
#pragma unroll
    for (int f = 0; f < 3; f++) {
        float u = s_b1[f];
#pragma unroll
        for (int d = 0; d < 6; d++) u += h2[d] * s_w1[f * 6 + d];
        g3[f] = 0.5f * u * (1.0f + erff(u * 0.70710678118654752f));
    }
#pragma unroll
    for (int d = 0; d < 6; d++) {
        float y = s_b2[d];
#pragma unroll
        for (int f = 0; f < 3; f++) y += g3[f] * s_w2[d * 3 + f];
        xa[d] += y;
    }

    // ---- final LN + fused logits ----
    float xf[6];
    ln6(xa, s_lfg, s_lfb, xf);

    float* so = &s_out[(r * T_SEQ + t) * VCB];
#pragma unroll
    for (int v = 0; v < VCB; v++) {
        float a = 0.0f;
#pragma unroll
        for (int d = 0; d < 6; d++) a += xf[d] * s_wlog[v * 6 + d];
        so[v] = a;
    }
    __syncthreads();

    // ---- coalesced block-contiguous output write ----
    float4* dst = (float4*)(out + (size_t)blockIdx.x * (ROWS * T_SEQ * VCB));
    const float4* src = (const float4*)s_out;
#pragma unroll 4
    for (int i = tid; i < (ROWS * T_SEQ * VCB) / 4; i += NT) dst[i] = src[i];
}

extern "C" void kernel_launch(void* const* d_in, const int* in_sizes, int n_in,
                              void* d_out, int out_size) {
    const int* idx = (const int*)d_in[0];
    const float* tok_emb = (const float*)d_in[1];
    const float* pos_enc = (const float*)d_in[2];
    const float* q_w = (const float*)d_in[3];
    const float* k_w = (const float*)d_in[4];
    const float* v_w = (const float*)d_in[5];
    const float* out_w = (const float*)d_in[6];
    const float* ln1_g = (const float*)d_in[7];
    const float* ln1_b = (const float*)d_in[8];
    const float* ln2_g = (const float*)d_in[9];
    const float* ln2_b = (const float*)d_in[10];
    const float* lnf_g = (const float*)d_in[11];
    const float* lnf_b = (const float*)d_in[12];
    const float* ffn_w1 = (const float*)d_in[13];
    const float* ffn_b1 = (const float*)d_in[14];
    const float* ffn_w2 = (const float*)d_in[15];
    const float* ffn_b2 = (const float*)d_in[16];
    const float* head_w = (const float*)d_in[17];
    float* out = (float*)d_out;

    const int B = in_sizes[0] / T_SEQ;          // 65536
    dim3 block(ROWS, T_SEQ);
    dim3 grid(B / ROWS);
    add_tf_kernel<<<grid, block>>>(idx, tok_emb, pos_enc, q_w, k_w, v_w, out_w,
                                   ln1_g, ln1_b, ln2_g, ln2_b, lnf_g, lnf_b,
                                   ffn_w1, ffn_b1, ffn_w2, ffn_b2, head_w, out);
}

// round 2
// speedup vs baseline: 1.1376x; 1.1376x over previous
#include <cuda_runtime.h>

typedef unsigned long long u64;

#define T_SEQ 34
#define RWS 16          // rows per block
#define TH 17           // paired positions per row: thread t handles t and 33-t
#define NT (RWS * TH)   // 272 threads
#define VCB 14

__device__ __forceinline__ u64 pk2(float lo, float hi) {
    u64 r; asm("mov.b64 %0, {%1, %2};" : "=l"(r) : "f"(lo), "f"(hi)); return r;
}
__device__ __forceinline__ void up2(u64 v, float& a, float& b) {
    asm("mov.b64 {%0, %1}, %2;" : "=f"(a), "=f"(b) : "l"(v));
}
__device__ __forceinline__ u64 f2fma(u64 a, u64 b, u64 c) {
    u64 d; asm("fma.rn.f32x2 %0, %1, %2, %3;" : "=l"(d) : "l"(a), "l"(b), "l"(c)); return d;
}
__device__ __forceinline__ u64 f2add(u64 a, u64 b) {
    u64 d; asm("add.rn.f32x2 %0, %1, %2;" : "=l"(d) : "l"(a), "l"(b)); return d;
}
__device__ __forceinline__ u64 f2mul(u64 a, u64 b) {
    u64 d; asm("mul.rn.f32x2 %0, %1, %2;" : "=l"(d) : "l"(a), "l"(b)); return d;
}
__device__ __forceinline__ u64 ld2(const float2* p) { return *(const u64*)p; }

// packed LayerNorm over 6 dims; lanes = two independent tokens
__device__ __forceinline__ void ln6p(const u64* x, const float2* g, const float2* b, u64* o) {
    u64 s = f2add(f2add(f2add(x[0], x[1]), f2add(x[2], x[3])), f2add(x[4], x[5]));
    u64 negmu = f2mul(s, pk2(-1.0f / 6.0f, -1.0f / 6.0f));
    u64 d0 = f2add(x[0], negmu), d1 = f2add(x[1], negmu), d2 = f2add(x[2], negmu);
    u64 d3 = f2add(x[3], negmu), d4 = f2add(x[4], negmu), d5 = f2add(x[5], negmu);
    u64 v = f2mul(d0, d0);
    v = f2fma(d1, d1, v); v = f2fma(d2, d2, v);
    v = f2fma(d3, d3, v); v = f2fma(d4, d4, v); v = f2fma(d5, d5, v);
    float va, vb; up2(v, va, vb);
    float ia = rsqrtf(va * (1.0f / 6.0f) + 1e-5f);
    float ib = rsqrtf(vb * (1.0f / 6.0f) + 1e-5f);
    u64 inv = pk2(ia, ib);
    o[0] = f2fma(f2mul(d0, inv), ld2(g + 0), ld2(b + 0));
    o[1] = f2fma(f2mul(d1, inv), ld2(g + 1), ld2(b + 1));
    o[2] = f2fma(f2mul(d2, inv), ld2(g + 2), ld2(b + 2));
    o[3] = f2fma(f2mul(d3, inv), ld2(g + 3), ld2(b + 3));
    o[4] = f2fma(f2mul(d4, inv), ld2(g + 4), ld2(b + 4));
    o[5] = f2fma(f2mul(d5, inv), ld2(g + 5), ld2(b + 5));
}

__global__ __launch_bounds__(NT) void add_tf_kernel(
    const int* __restrict__ idx,
    const float* __restrict__ tok_emb, const float* __restrict__ pos_enc,
    const float* __restrict__ qw, const float* __restrict__ kw, const float* __restrict__ vw,
    const float* __restrict__ outw,
    const float* __restrict__ ln1g, const float* __restrict__ ln1b,
    const float* __restrict__ ln2g, const float* __restrict__ ln2b,
    const float* __restrict__ lnfg, const float* __restrict__ lnfb,
    const float* __restrict__ fw1, const float* __restrict__ fb1,
    const float* __restrict__ fw2, const float* __restrict__ fb2,
    const float* __restrict__ headw,
    float* __restrict__ out)
{
    __shared__ float s_te[42], s_pe[102];
    __shared__ __align__(8) float2 s_qw2[18], s_kw2[18], s_vw2[18], s_ow2[36];
    __shared__ __align__(8) float2 s_w12[18], s_w22[18], s_b12[3], s_b22[6];
    __shared__ __align__(8) float2 s_l1g2[6], s_l1b2[6], s_l2g2[6], s_l2b2[6], s_lfg2[6], s_lfb2[6];
    __shared__ __align__(8) float2 s_wlog2[84];
    // K/V buffer and output staging are live in disjoint phases -> union
    __shared__ union {
        float4 kv[RWS][T_SEQ][3];          // head-packed: {k0h0,k0h1,k1h0,k1h1},{k2h0,k2h1,v0h0,v0h1},{v1h0,v1h1,v2h0,v2h1}
        float ob[RWS * T_SEQ * VCB];
    } uni;

    const int r = threadIdx.x;      // row in block (0..15)
    const int t = threadIdx.y;      // position pair index (0..16)
    const int tid = t * RWS + r;
    const float rs3 = 0.57735026918962576f;

    // ---- stage weights (duplicated pairs for packed math) ----
    for (int i = tid; i < 42; i += NT) s_te[i] = tok_emb[i];
    for (int i = tid; i < 102; i += NT) s_pe[i] = pos_enc[i];
    for (int i = tid; i < 18; i += NT) {
        float a = qw[i] * rs3; s_qw2[i] = make_float2(a, a);   // fold 1/sqrt(d) into q
        float b = kw[i];       s_kw2[i] = make_float2(b, b);
        float c = vw[i];       s_vw2[i] = make_float2(c, c);
        float d = fw1[i];      s_w12[i] = make_float2(d, d);
        float e = fw2[i];      s_w22[i] = make_float2(e, e);
    }
    for (int i = tid; i < 36; i += NT) { float a = outw[i]; s_ow2[i] = make_float2(a, a); }
    for (int i = tid; i < 6; i += NT) {
        float a = ln1g[i]; s_l1g2[i] = make_float2(a, a);
        float b = ln1b[i]; s_l1b2[i] = make_float2(b, b);
        float c = ln2g[i]; s_l2g2[i] = make_float2(c, c);
        float d = ln2b[i]; s_l2b2[i] = make_float2(d, d);
        float e = lnfg[i]; s_lfg2[i] = make_float2(e, e);
        float f = lnfb[i]; s_lfb2[i] = make_float2(f, f);
        float g = fb2[i];  s_b22[i]  = make_float2(g, g);
    }
    for (int i = tid; i < 3; i += NT) { float a = fb1[i]; s_b12[i] = make_float2(a, a); }
    __syncthreads();

    // fused logits matrix Wlog[v][d] = sum_c tok_emb[v][c] * head_w[c][d], duplicated
    for (int i = tid; i < 84; i += NT) {
        int v = i / 6, d = i % 6;
        float w = s_te[v * 3 + 0] * headw[0 * 6 + d]
                + s_te[v * 3 + 1] * headw[1 * 6 + d]
                + s_te[v * 3 + 2] * headw[2 * 6 + d];
        s_wlog2[i] = make_float2(w, w);
    }

    // ---- per-thread: two tokens, positions tA=t and tB=33-t ----
    const int b = blockIdx.x * RWS + r;
    const int tA = t, tB = 33 - t;
    const int tokA = idx[(size_t)b * T_SEQ + tA];
    const int tokB = idx[(size_t)b * T_SEQ + tB];

    u64 x2[6];  // lanes = (tokenA, tokenB)
    x2[0] = pk2(s_te[tokA * 3 + 0], s_te[tokB * 3 + 0]);
    x2[1] = pk2(s_te[tokA * 3 + 1], s_te[tokB * 3 + 1]);
    x2[2] = pk2(s_te[tokA * 3 + 2], s_te[tokB * 3 + 2]);
    x2[3] = pk2(s_pe[tA * 3 + 0], s_pe[tB * 3 + 0]);
    x2[4] = pk2(s_pe[tA * 3 + 1], s_pe[tB * 3 + 1]);
    x2[5] = pk2(s_pe[tA * 3 + 2], s_pe[tB * 3 + 2]);

    u64 h1[6];
    ln6p(x2, s_l1g2, s_l1b2, h1);

    u64 q2[6], k2[6], v2[6];
#pragma unroll
    for (int o = 0; o < 6; o++) {
        q2[o] = f2fma(h1[5], ld2(&s_qw2[o * 3 + 2]),
                f2fma(h1[4], ld2(&s_qw2[o * 3 + 1]),
                f2mul(h1[3], ld2(&s_qw2[o * 3 + 0]))));
        k2[o] = f2fma(h1[5], ld2(&s_kw2[o * 3 + 2]),
                f2fma(h1[4], ld2(&s_kw2[o * 3 + 1]),
                f2mul(h1[3], ld2(&s_kw2[o * 3 + 0]))));
        v2[o] = f2fma(h1[2], ld2(&s_vw2[o * 3 + 2]),
                f2fma(h1[1], ld2(&s_vw2[o * 3 + 1]),
                f2mul(h1[0], ld2(&s_vw2[o * 3 + 0]))));
    }

    // unpack token lanes; build head-packed q per token
    float qA[6], qB[6], kA[6], kB[6], vA[6], vB[6];
#pragma unroll
    for (int o = 0; o < 6; o++) {
        up2(q2[o], qA[o], qB[o]);
        up2(k2[o], kA[o], kB[o]);
        up2(v2[o], vA[o], vB[o]);
    }
    u64 qhA0 = pk2(qA[0], qA[3]), qhA1 = pk2(qA[1], qA[4]), qhA2 = pk2(qA[2], qA[5]);
    u64 qhB0 = pk2(qB[0], qB[3]), qhB1 = pk2(qB[1], qB[4]), qhB2 = pk2(qB[2], qB[5]);

    // store K/V head-packed for both tokens
    {
        float4* p = &uni.kv[r][tA][0];
        p[0] = make_float4(kA[0], kA[3], kA[1], kA[4]);
        p[1] = make_float4(kA[2], kA[5], vA[0], vA[3]);
        p[2] = make_float4(vA[1], vA[4], vA[2], vA[5]);
        float4* pb = &uni.kv[r][tB][0];
        pb[0] = make_float4(kB[0], kB[3], kB[1], kB[4]);
        pb[1] = make_float4(kB[2], kB[5], vB[0], vB[3]);
        pb[2] = make_float4(vB[1], vB[4], vB[2], vB[5]);
    }
    __syncthreads();

    // ---- causal attention, lanes = heads, one pass serves both tokens ----
    u64 ssA = 0ULL, aA0 = 0ULL, aA1 = 0ULL, aA2 = 0ULL;
    u64 ssB = 0ULL, aB0 = 0ULL, aB1 = 0ULL, aB2 = 0ULL;
    const int jmax = tB;   // 33 - t >= t
    for (int j = 0; j <= jmax; j++) {
        const float4* p = &uni.kv[r][j][0];
        float4 P0 = p[0], P1 = p[1], P2 = p[2];
        u64 kk0 = pk2(P0.x, P0.y), kk1 = pk2(P0.z, P0.w), kk2 = pk2(P1.x, P1.y);
        u64 vv0 = pk2(P1.z, P1.w), vv1 = pk2(P2.x, P2.y), vv2 = pk2(P2.z, P2.w);

        // token B (always in range)
        u64 sB = f2fma(qhB2, kk2, f2fma(qhB1, kk1, f2mul(qhB0, kk0)));
        float sb0, sb1; up2(sB, sb0, sb1);
        u64 eB = pk2(__expf(sb0), __expf(sb1));
        ssB = f2add(ssB, eB);
        aB0 = f2fma(eB, vv0, aB0); aB1 = f2fma(eB, vv1, aB1); aB2 = f2fma(eB, vv2, aB2);

        if (j <= t) {  // token A
            u64 sA = f2fma(qhA2, kk2, f2fma(qhA1, kk1, f2mul(qhA0, kk0)));
            float sa0, sa1; up2(sA, sa0, sa1);
            u64 eA = pk2(__expf(sa0), __expf(sa1));
            ssA = f2add(ssA, eA);
            aA0 = f2fma(eA, vv0, aA0); aA1 = f2fma(eA, vv1, aA1); aA2 = f2fma(eA, vv2, aA2);
        }
    }
    __syncthreads();   // kv -> ob buffer reuse

    // normalize; rebuild token-packed attention output o2[6]
    float oA[6], oB[6];
    {
        float s0, s1; up2(ssA, s0, s1);
        float i0 = __fdividef(1.0f, s0), i1 = __fdividef(1.0f, s1);
        float a, c;
        up2(aA0, a, c); oA[0] = a * i0; oA[3] = c * i1;
        up2(aA1, a, c); oA[1] = a * i0; oA[4] = c * i1;
        up2(aA2, a, c); oA[2] = a * i0; oA[5] = c * i1;
        up2(ssB, s0, s1);
        i0 = __fdividef(1.0f, s0); i1 = __fdividef(1.0f, s1);
        up2(aB0, a, c); oB[0] = a * i0; oB[3] = c * i1;
        up2(aB1, a, c); oB[1] = a * i0; oB[4] = c * i1;
        up2(aB2, a, c); oB[2] = a * i0; oB[5] = c * i1;
    }
    u64 o2[6];
#pragma unroll
    for (int o = 0; o < 6; o++) o2[o] = pk2(oA[o], oB[o]);

    // out-proj + residual (packed across tokens)
    u64 xa[6];
#pragma unroll
    for (int d = 0; d < 6; d++) {
        u64 a = x2[d];
#pragma unroll
        for (int o = 0; o < 6; o++) a = f2fma(o2[o], ld2(&s_ow2[d * 6 + o]), a);
        xa[d] = a;
    }

    // FFN (exact GELU) + residual
    u64 h2[6];
    ln6p(xa, s_l2g2, s_l2b2, h2);
    u64 g2[3];
#pragma unroll
    for (int f = 0; f < 3; f++) {
        u64 u = ld2(&s_b12[f]);
#pragma unroll
        for (int d = 0; d < 6; d++) u = f2fma(h2[d], ld2(&s_w12[f * 6 + d]), u);
        float ua, ub; up2(u, ua, ub);
        float ga = 0.5f * ua * (1.0f + erff(ua * 0.70710678118654752f));
        float gb = 0.5f * ub * (1.0f + erff(ub * 0.70710678118654752f));
        g2[f] = pk2(ga, gb);
    }
#pragma unroll
    for (int d = 0; d < 6; d++) {
        u64 y = ld2(&s_b22[d]);
#pragma unroll
        for (int f = 0; f < 3; f++) y = f2fma(g2[f], ld2(&s_w22[d * 3 + f]), y);
        xa[d] = f2add(xa[d], y);
    }

    // final LN + fused logits
    u64 xf[6];
    ln6p(xa, s_lfg2, s_lfb2, xf);

    float* soA = &uni.ob[(r * T_SEQ + tA) * VCB];
    float* soB = &uni.ob[(r * T_SEQ + tB) * VCB];
#pragma unroll
    for (int v = 0; v < VCB; v++) {
        u64 acc = f2mul(xf[0], ld2(&s_wlog2[v * 6 + 0]));
#pragma unroll
        for (int d = 1; d < 6; d++) acc = f2fma(xf[d], ld2(&s_wlog2[v * 6 + d]), acc);
        float la, lb; up2(acc, la, lb);
        soA[v] = la; soB[v] = lb;
    }
    __syncthreads();

    // coalesced block-contiguous output write
    float4* dst = (float4*)(out + (size_t)blockIdx.x * (RWS * T_SEQ * VCB));
    const float4* src = (const float4*)uni.ob;
#pragma unroll
    for (int i = tid; i < (RWS * T_SEQ * VCB) / 4; i += NT) dst[i] = src[i];
}

extern "C" void kernel_launch(void* const* d_in, const int* in_sizes, int n_in,
                              void* d_out, int out_size) {
    const int* idx = (const int*)d_in[0];
    const float* tok_emb = (const float*)d_in[1];
    const float* pos_enc = (const float*)d_in[2];
    const float* q_w = (const float*)d_in[3];
    const float* k_w = (const float*)d_in[4];
    const float* v_w = (const float*)d_in[5];
    const float* out_w = (const float*)d_in[6];
    const float* ln1_g = (const float*)d_in[7];
    const float* ln1_b = (const float*)d_in[8];
    const float* ln2_g = (const float*)d_in[9];
    const float* ln2_b = (const float*)d_in[10];
    const float* lnf_g = (const float*)d_in[11];
    const float* lnf_b = (const float*)d_in[12];
    const float* ffn_w1 = (const float*)d_in[13];
    const float* ffn_b1 = (const float*)d_in[14];
    const float* ffn_w2 = (const float*)d_in[15];
    const float* ffn_b2 = (const float*)d_in[16];
    const float* head_w = (const float*)d_in[17];
    float* out = (float*)d_out;

    const int B = in_sizes[0] / T_SEQ;   // 65536
    dim3 block(RWS, TH);
    dim3 grid(B / RWS);
    add_tf_kernel<<<grid, block>>>(idx, tok_emb, pos_enc, q_w, k_w, v_w, out_w,
                                   ln1_g, ln1_b, ln2_g, ln2_b, lnf_g, lnf_b,
                                   ffn_w1, ffn_b1, ffn_w2, ffn_b2, head_w, out);
}

// round 3
// speedup vs baseline: 1.6140x; 1.4188x over previous
#include <cuda_runtime.h>

typedef unsigned long long u64;

#define T_SEQ 34
#define RWS 16          // rows per block
#define TH 17           // paired positions: thread t handles t and 33-t
#define NT (RWS * TH)   // 272 threads
#define VCB 14

// ---- constant-packed weights (duplicated float2 for f32x2 math) ----
// layout (float2 index):
//  0 qw(18) | 18 kw(18) | 36 vw(18) | 54 ow(36) | 90 w1(18) | 108 w2(18)
//  126 b1(3) | 129 b2(6) | 135 l1g(6) 141 l1b(6) 147 l2g(6) 153 l2b(6)
//  159 lfg(6) 165 lfb(6) | 171 wlog(84)   -> total 255
#define NPK 255
__constant__ __align__(8) float2 c_pack[NPK];
__device__ __align__(8) float2 g_scratch[NPK];

__device__ __forceinline__ u64 pk2(float lo, float hi) {
    u64 r; asm("mov.b64 %0, {%1, %2};" : "=l"(r) : "f"(lo), "f"(hi)); return r;
}
__device__ __forceinline__ void up2(u64 v, float& a, float& b) {
    asm("mov.b64 {%0, %1}, %2;" : "=f"(a), "=f"(b) : "l"(v));
}
__device__ __forceinline__ u64 f2fma(u64 a, u64 b, u64 c) {
    u64 d; asm("fma.rn.f32x2 %0, %1, %2, %3;" : "=l"(d) : "l"(a), "l"(b), "l"(c)); return d;
}
__device__ __forceinline__ u64 f2add(u64 a, u64 b) {
    u64 d; asm("add.rn.f32x2 %0, %1, %2;" : "=l"(d) : "l"(a), "l"(b)); return d;
}
__device__ __forceinline__ u64 f2mul(u64 a, u64 b) {
    u64 d; asm("mul.rn.f32x2 %0, %1, %2;" : "=l"(d) : "l"(a), "l"(b)); return d;
}
__device__ __forceinline__ u64 cw(int i) {
    return *reinterpret_cast<const u64*>(&c_pack[i]);
}

// packed LayerNorm over 6 dims; lanes = two independent tokens
__device__ __forceinline__ void ln6p(const u64* x, int gi, int bi, u64* o) {
    u64 s = f2add(f2add(f2add(x[0], x[1]), f2add(x[2], x[3])), f2add(x[4], x[5]));
    u64 negmu = f2mul(s, pk2(-1.0f / 6.0f, -1.0f / 6.0f));
    u64 d0 = f2add(x[0], negmu), d1 = f2add(x[1], negmu), d2 = f2add(x[2], negmu);
    u64 d3 = f2add(x[3], negmu), d4 = f2add(x[4], negmu), d5 = f2add(x[5], negmu);
    u64 v = f2mul(d0, d0);
    v = f2fma(d1, d1, v); v = f2fma(d2, d2, v);
    v = f2fma(d3, d3, v); v = f2fma(d4, d4, v); v = f2fma(d5, d5, v);
    float va, vb; up2(v, va, vb);
    float ia = rsqrtf(va * (1.0f / 6.0f) + 1e-5f);
    float ib = rsqrtf(vb * (1.0f / 6.0f) + 1e-5f);
    u64 inv = pk2(ia, ib);
    o[0] = f2fma(f2mul(d0, inv), cw(gi + 0), cw(bi + 0));
    o[1] = f2fma(f2mul(d1, inv), cw(gi + 1), cw(bi + 1));
    o[2] = f2fma(f2mul(d2, inv), cw(gi + 2), cw(bi + 2));
    o[3] = f2fma(f2mul(d3, inv), cw(gi + 3), cw(bi + 3));
    o[4] = f2fma(f2mul(d4, inv), cw(gi + 4), cw(bi + 4));
    o[5] = f2fma(f2mul(d5, inv), cw(gi + 5), cw(bi + 5));
}

__global__ void prep_kernel(
    const float* __restrict__ tok_emb,
    const float* __restrict__ qw, const float* __restrict__ kw, const float* __restrict__ vw,
    const float* __restrict__ outw,
    const float* __restrict__ ln1g, const float* __restrict__ ln1b,
    const float* __restrict__ ln2g, const float* __restrict__ ln2b,
    const float* __restrict__ lnfg, const float* __restrict__ lnfb,
    const float* __restrict__ fw1, const float* __restrict__ fb1,
    const float* __restrict__ fw2, const float* __restrict__ fb2,
    const float* __restrict__ headw)
{
    int i = threadIdx.x;
    if (i >= NPK) return;
    const float rs3 = 0.57735026918962576f;
    float lo;
    if (i < 18)       lo = qw[i] * rs3;
    else if (i < 36)  lo = kw[i - 18];
    else if (i < 54)  lo = vw[i - 36];
    else if (i < 90)  lo = outw[i - 54];
    else if (i < 108) lo = fw1[i - 90];
    else if (i < 126) lo = fw2[i - 108];
    else if (i < 129) lo = fb1[i - 126];
    else if (i < 135) lo = fb2[i - 129];
    else if (i < 141) lo = ln1g[i - 135];
    else if (i < 147) lo = ln1b[i - 141];
    else if (i < 153) lo = ln2g[i - 147];
    else if (i < 159) lo = ln2b[i - 153];
    else if (i < 165) lo = lnfg[i - 159];
    else if (i < 171) lo = lnfb[i - 165];
    else {
        int v = (i - 171) / 6, d = (i - 171) % 6;
        lo = tok_emb[v * 3 + 0] * headw[0 * 6 + d]
           + tok_emb[v * 3 + 1] * headw[1 * 6 + d]
           + tok_emb[v * 3 + 2] * headw[2 * 6 + d];
    }
    g_scratch[i] = make_float2(lo, lo);
}

__global__ __launch_bounds__(NT) void add_tf_kernel(
    const int* __restrict__ idx,
    const float* __restrict__ tok_emb, const float* __restrict__ pos_enc,
    float* __restrict__ out)
{
    __shared__ float s_te[42], s_pe[102];
    __shared__ int s_idx[RWS * T_SEQ];            // 544 ints
    // KV: [row][j*3+c], row stride 105 float4 = 420 words == 4 (mod 32) -> conflict-free
    __shared__ union {
        float4 kv[RWS][105];
        float ob[RWS * T_SEQ * VCB];              // 7616 floats
    } uni;

    const int r = threadIdx.x;      // row in block (0..15)
    const int t = threadIdx.y;      // pair index (0..16)
    const int tid = t * RWS + r;

    // ---- stage embeddings + idx (coalesced) ----
    for (int i = tid; i < 42; i += NT) s_te[i] = tok_emb[i];
    for (int i = tid; i < 102; i += NT) s_pe[i] = pos_enc[i];
    {
        const int4* gsrc = (const int4*)(idx + (size_t)blockIdx.x * (RWS * T_SEQ));
        int4* sdst = (int4*)s_idx;
        for (int i = tid; i < (RWS * T_SEQ) / 4; i += NT) sdst[i] = gsrc[i];
    }
    __syncthreads();

    const int tA = t, tB = 33 - t;
    const int tokA = s_idx[r * T_SEQ + tA];
    const int tokB = s_idx[r * T_SEQ + tB];

    u64 x2[6];  // lanes = (tokenA, tokenB)
    x2[0] = pk2(s_te[tokA * 3 + 0], s_te[tokB * 3 + 0]);
    x2[1] = pk2(s_te[tokA * 3 + 1], s_te[tokB * 3 + 1]);
    x2[2] = pk2(s_te[tokA * 3 + 2], s_te[tokB * 3 + 2]);
    x2[3] = pk2(s_pe[tA * 3 + 0], s_pe[tB * 3 + 0]);
    x2[4] = pk2(s_pe[tA * 3 + 1], s_pe[tB * 3 + 1]);
    x2[5] = pk2(s_pe[tA * 3 + 2], s_pe[tB * 3 + 2]);

    u64 h1[6];
    ln6p(x2, 135, 141, h1);

    u64 q2[6], k2[6], v2[6];
#pragma unroll
    for (int o = 0; o < 6; o++) {
        q2[o] = f2fma(h1[5], cw(0 + o * 3 + 2),
                f2fma(h1[4], cw(0 + o * 3 + 1),
                f2mul(h1[3], cw(0 + o * 3 + 0))));
        k2[o] = f2fma(h1[5], cw(18 + o * 3 + 2),
                f2fma(h1[4], cw(18 + o * 3 + 1),
                f2mul(h1[3], cw(18 + o * 3 + 0))));
        v2[o] = f2fma(h1[2], cw(36 + o * 3 + 2),
                f2fma(h1[1], cw(36 + o * 3 + 1),
                f2mul(h1[0], cw(36 + o * 3 + 0))));
    }

    float qA[6], qB[6], kA[6], kB[6], vA[6], vB[6];
#pragma unroll
    for (int o = 0; o < 6; o++) {
        up2(q2[o], qA[o], qB[o]);
        up2(k2[o], kA[o], kB[o]);
        up2(v2[o], vA[o], vB[o]);
    }
    u64 qhA0 = pk2(qA[0], qA[3]), qhA1 = pk2(qA[1], qA[4]), qhA2 = pk2(qA[2], qA[5]);
    u64 qhB0 = pk2(qB[0], qB[3]), qhB1 = pk2(qB[1], qB[4]), qhB2 = pk2(qB[2], qB[5]);

    {
        float4* p = &uni.kv[r][tA * 3];
        p[0] = make_float4(kA[0], kA[3], kA[1], kA[4]);
        p[1] = make_float4(kA[2], kA[5], vA[0], vA[3]);
        p[2] = make_float4(vA[1], vA[4], vA[2], vA[5]);
        float4* pb = &uni.kv[r][tB * 3];
        pb[0] = make_float4(kB[0], kB[3], kB[1], kB[4]);
        pb[1] = make_float4(kB[2], kB[5], vB[0], vB[3]);
        pb[2] = make_float4(vB[1], vB[4], vB[2], vB[5]);
    }
    __syncthreads();

    // ---- causal attention, lanes = heads, one KV pass serves both tokens ----
    u64 ssA = 0ULL, aA0 = 0ULL, aA1 = 0ULL, aA2 = 0ULL;
    u64 ssB = 0ULL, aB0 = 0ULL, aB1 = 0ULL, aB2 = 0ULL;
    const int jmax = tB;
    for (int j = 0; j <= jmax; j++) {
        const float4* p = &uni.kv[r][j * 3];
        float4 P0 = p[0], P1 = p[1], P2 = p[2];
        u64 kk0 = pk2(P0.x, P0.y), kk1 = pk2(P0.z, P0.w), kk2 = pk2(P1.x, P1.y);
        u64 vv0 = pk2(P1.z, P1.w), vv1 = pk2(P2.x, P2.y), vv2 = pk2(P2.z, P2.w);

        u64 sB = f2fma(qhB2, kk2, f2fma(qhB1, kk1, f2mul(qhB0, kk0)));
        float sb0, sb1; up2(sB, sb0, sb1);
        u64 eB = pk2(__expf(sb0), __expf(sb1));
        ssB = f2add(ssB, eB);
        aB0 = f2fma(eB, vv0, aB0); aB1 = f2fma(eB, vv1, aB1); aB2 = f2fma(eB, vv2, aB2);

        if (j <= t) {
            u64 sA = f2fma(qhA2, kk2, f2fma(qhA1, kk1, f2mul(qhA0, kk0)));
            float sa0, sa1; up2(sA, sa0, sa1);
            u64 eA = pk2(__expf(sa0), __expf(sa1));
            ssA = f2add(ssA, eA);
            aA0 = f2fma(eA, vv0, aA0); aA1 = f2fma(eA, vv1, aA1); aA2 = f2fma(eA, vv2, aA2);
        }
    }
    __syncthreads();   // kv -> ob buffer reuse

    float oA[6], oB[6];
    {
        float s0, s1; up2(ssA, s0, s1);
        float i0 = __fdividef(1.0f, s0), i1 = __fdividef(1.0f, s1);
        float a, c;
        up2(aA0, a, c); oA[0] = a * i0; oA[3] = c * i1;
        up2(aA1, a, c); oA[1] = a * i0; oA[4] = c * i1;
        up2(aA2, a, c); oA[2] = a * i0; oA[5] = c * i1;
        up2(ssB, s0, s1);
        i0 = __fdividef(1.0f, s0); i1 = __fdividef(1.0f, s1);
        up2(aB0, a, c); oB[0] = a * i0; oB[3] = c * i1;
        up2(aB1, a, c); oB[1] = a * i0; oB[4] = c * i1;
        up2(aB2, a, c); oB[2] = a * i0; oB[5] = c * i1;
    }
    u64 o2[6];
#pragma unroll
    for (int o = 0; o < 6; o++) o2[o] = pk2(oA[o], oB[o]);

    // out-proj + residual
    u64 xa[6];
#pragma unroll
    for (int d = 0; d < 6; d++) {
        u64 a = x2[d];
#pragma unroll
        for (int o = 0; o < 6; o++) a = f2fma(o2[o], cw(54 + d * 6 + o), a);
        xa[d] = a;
    }

    // FFN (exact GELU) + residual
    u64 h2[6];
    ln6p(xa, 147, 153, h2);
    u64 g2[3];
#pragma unroll
    for (int f = 0; f < 3; f++) {
        u64 u = cw(126 + f);
#pragma unroll
        for (int d = 0; d < 6; d++) u = f2fma(h2[d], cw(90 + f * 6 + d), u);
        float ua, ub; up2(u, ua, ub);
        float ga = 0.5f * ua * (1.0f + erff(ua * 0.70710678118654752f));
        float gb = 0.5f * ub * (1.0f + erff(ub * 0.70710678118654752f));
        g2[f] = pk2(ga, gb);
    }
#pragma unroll
    for (int d = 0; d < 6; d++) {
        u64 y = cw(129 + d);
#pragma unroll
        for (int f = 0; f < 3; f++) y = f2fma(g2[f], cw(108 + d * 3 + f), y);
        xa[d] = f2add(xa[d], y);
    }

    // final LN + fused logits
    u64 xf[6];
    ln6p(xa, 159, 165, xf);

    float* soA = &uni.ob[(r * T_SEQ + tA) * VCB];
    float* soB = &uni.ob[(r * T_SEQ + tB) * VCB];
#pragma unroll
    for (int v = 0; v < VCB; v++) {
        u64 acc = f2mul(xf[0], cw(171 + v * 6 + 0));
#pragma unroll
        for (int d = 1; d < 6; d++) acc = f2fma(xf[d], cw(171 + v * 6 + d), acc);
        float la, lb; up2(acc, la, lb);
        soA[v] = la; soB[v] = lb;
    }
    __syncthreads();

    // coalesced block-contiguous output write
    float4* dst = (float4*)(out + (size_t)blockIdx.x * (RWS * T_SEQ * VCB));
    const float4* src = (const float4*)uni.ob;
#pragma unroll
    for (int i = tid; i < (RWS * T_SEQ * VCB) / 4; i += NT) dst[i] = src[i];
}

extern "C" void kernel_launch(void* const* d_in, const int* in_sizes, int n_in,
                              void* d_out, int out_size) {
    const int* idx = (const int*)d_in[0];
    const float* tok_emb = (const float*)d_in[1];
    const float* pos_enc = (const float*)d_in[2];
    const float* q_w = (const float*)d_in[3];
    const float* k_w = (const float*)d_in[4];
    const float* v_w = (const float*)d_in[5];
    const float* out_w = (const float*)d_in[6];
    const float* ln1_g = (const float*)d_in[7];
    const float* ln1_b = (const float*)d_in[8];
    const float* ln2_g = (const float*)d_in[9];
    const float* ln2_b = (const float*)d_in[10];
    const float* lnf_g = (const float*)d_in[11];
    const float* lnf_b = (const float*)d_in[12];
    const float* ffn_w1 = (const float*)d_in[13];
    const float* ffn_b1 = (const float*)d_in[14];
    const float* ffn_w2 = (const float*)d_in[15];
    const float* ffn_b2 = (const float*)d_in[16];
    const float* head_w = (const float*)d_in[17];
    float* out = (float*)d_out;

    prep_kernel<<<1, 256>>>(tok_emb, q_w, k_w, v_w, out_w,
                            ln1_g, ln1_b, ln2_g, ln2_b, lnf_g, lnf_b,
                            ffn_w1, ffn_b1, ffn_w2, ffn_b2, head_w);

    void* scratch_ptr = nullptr;
    cudaGetSymbolAddress(&scratch_ptr, g_scratch);
    cudaMemcpyToSymbolAsync(c_pack, scratch_ptr, NPK * sizeof(float2), 0,
                            cudaMemcpyDeviceToDevice, 0);

    const int B = in_sizes[0] / T_SEQ;   // 65536
    dim3 block(RWS, TH);
    dim3 grid(B / RWS);
    add_tf_kernel<<<grid, block>>>(idx, tok_emb, pos_enc, out);
}